// round 7
// baseline (speedup 1.0000x reference)
#include <cuda_runtime.h>
#include <cuda_bf16.h>

// N=1, C=2, H=64, W=64, D=32, radius=(3,3,1), SIGMA_XY=5, SIGMA_IMG=0.1, WEIGHT=1
#define NH 64
#define NW 64
#define ND 32
#define NL (NH * NW * ND)      // 131072

#define TPB  256
#define NBLK 1024              // block = (h=1, w=4, d=32) slab = 128 voxels, 2 threads/voxel

// smem tile: h 7 x w 10 x d 34 halo'd neighborhood, packed (s, y0)
#define TH 7
#define TW 10
#define TD 34
#define TSTRW TD               // 34
#define TSTRH (TW * TD)        // 340
#define TSIZE (TH * TW * TD)   // 2380

#define SENTINEL 1e19f
#define LOG2E 1.4426950408889634f
#define NTAPS 73
#define TAPSPLIT 37

__device__ float    g_part[NBLK];
__device__ unsigned g_cnt = 0;   // last block resets to 0 (graph-replay safe)

__device__ __forceinline__ float ex2(float x) {   // guaranteed MUFU EX2
    float r;
    asm("ex2.approx.f32 %0, %1;" : "=f"(r) : "f"(x));
    return r;
}

// Compile-time tap-range walker: half-space offsets (73 of 146 non-center
// taps); each in-bounds pair counted once (doubled by caller) — kernel and
// (1-dot) are p<->q symmetric. Sentinel halo drives ex2 -> exactly 0, so the
// body is branch-free immediate-offset LDS.
template<int LO, int HI>
__device__ __forceinline__ void do_taps(const float2* __restrict__ tile, int tb,
                                        float sp, float aH, float aW, float aD, float c2,
                                        float& K0, float& K1, float& KY0, float& KY1) {
    int tap = 0;
    #pragma unroll
    for (int dz = 0; dz <= 1; ++dz) {
        #pragma unroll
        for (int dw = -3; dw <= 3; ++dw) {
            #pragma unroll
            for (int dh = -3; dh <= 3; ++dh) {
                if (dz == 0 && (dw < 0 || (dw == 0 && dh <= 0))) continue;
                if (tap >= LO && tap < HI) {          // compile-time: LO/HI/tap all const
                    const float2 cq = tile[tb + dh * TSTRH + dw * TSTRW + dz];
                    const float coff = -(aH * (float)(dh * dh)
                                       + aW * (float)(dw * dw)
                                       + aD * (float)(dz * dz));   // CSE'd constants
                    const float ds = sp - cq.x;
                    const float e2 = fmaf(c2 * ds, ds, coff);
                    const float k  = ex2(e2);
                    if (tap & 1) { K1 += k; KY1 = fmaf(k, cq.y, KY1); }
                    else         { K0 += k; KY0 = fmaf(k, cq.y, KY0); }
                }
                ++tap;
            }
        }
    }
}

__global__ __launch_bounds__(TPB) void k_all(const float* __restrict__ y,
                                             const float* __restrict__ s,
                                             const float* __restrict__ spacing,
                                             float* __restrict__ out) {
    __shared__ float2 tile[TSIZE];
    __shared__ float  warp_s[8];

    // block -> slab origin
    const int hbase = blockIdx.x >> 4;          // 0..63
    const int wbase = (blockIdx.x & 15) << 2;   // 0,4,...,60

    // ---- cooperative tile load (R5-style, branch-free predication) ----
    for (int i = threadIdx.x; i < TSIZE; i += TPB) {
        const int th = i / TSTRH;
        const int r  = i - th * TSTRH;
        const int tw = r / TD;
        const int td = r - tw * TD;
        const int gh = hbase + th - 3;
        const int gw = wbase + tw - 3;
        const int gd = td - 1;
        float2 v = make_float2(SENTINEL, 0.0f);
        if (((unsigned)gh < NH) & ((unsigned)gw < NW) & ((unsigned)gd < ND)) {
            const int gidx = (gh * NW + gw) * ND + gd;
            v = make_float2(__ldg(s + gidx), __ldg(y + gidx));
        }
        tile[i] = v;
    }
    __syncthreads();

    // thread -> voxel; threads tid and tid+128 share a voxel, split the taps
    const int d    = threadIdx.x & 31;
    const int wl   = (threadIdx.x >> 5) & 3;    // 0..3
    const int half = threadIdx.x >> 7;          // 0 or 1
    const int w    = wbase + wl;
    const int h    = hbase;
    const int tb   = 3 * TSTRH + (wl + 3) * TSTRW + (d + 1);

    const float2 c0 = tile[tb];
    const float sp  = c0.x;
    const float y0p = c0.y;
    const float m   = 1.0f - 2.0f * y0p;        // 1 - dot = y0p + m*y0q  (C=2 softmax)

    const float sH = __ldg(spacing + 0);
    const float sW = __ldg(spacing + 1);
    const float sD = __ldg(spacing + 2);
    const float aH = sH * sH * (LOG2E / 50.0f);
    const float aW = sW * sW * (LOG2E / 50.0f);
    const float aD = sD * sD * (LOG2E / 50.0f);
    const float c2 = -50.0f * LOG2E;

    float K0 = 0.0f, K1 = 0.0f, KY0 = 0.0f, KY1 = 0.0f;
    if (half == 0) {
        do_taps<0, TAPSPLIT>(tile, tb, sp, aH, aW, aD, c2, K0, K1, KY0, KY1);
    } else {
        do_taps<TAPSPLIT, NTAPS>(tile, tb, sp, aH, aW, aD, c2, K0, K1, KY0, KY1);
    }
    float acc = 2.0f * (y0p * (K0 + K1) + m * (KY0 + KY1));

    // OOB taps (zero-padded unfold): y-term 0; kernel value identical per
    // OOB offset: exp(-0.5*||f(p)||^2). Counted analytically; half 0 only.
    if (half == 0) {
        const int cntH = min(h, 3) + min(NH - 1 - h, 3) + 1;
        const int cntW = min(w, 3) + min(NW - 1 - w, 3) + 1;
        const int cntD = min(d, 1) + min(ND - 1 - d, 1) + 1;
        const int noob = 147 - cntH * cntW * cntD;
        if (noob) {
            const float e = -(aH * (float)(h * h) + aW * (float)(w * w) + aD * (float)(d * d))
                            + c2 * sp * sp;
            acc = fmaf((float)noob, ex2(e), acc);
        }
    }

    // ---- block reduction ----
    #pragma unroll
    for (int o = 16; o; o >>= 1) acc += __shfl_down_sync(0xffffffffu, acc, o);
    const int lane = threadIdx.x & 31;
    const int wrp  = threadIdx.x >> 5;
    if (lane == 0) warp_s[wrp] = acc;
    __syncthreads();
    if (threadIdx.x == 0) {
        float b = 0.0f;
        #pragma unroll
        for (int j = 0; j < 8; ++j) b += warp_s[j];
        g_part[blockIdx.x] = b;
    }

    // ---- last-block final reduction ----
    __threadfence();
    __shared__ bool is_last;
    if (threadIdx.x == 0)
        is_last = (atomicAdd(&g_cnt, 1u) == NBLK - 1);
    __syncthreads();

    if (is_last) {
        float v = 0.0f;
        #pragma unroll
        for (int j = 0; j < NBLK / TPB; ++j)
            v += g_part[threadIdx.x + j * TPB];
        #pragma unroll
        for (int o = 16; o; o >>= 1) v += __shfl_down_sync(0xffffffffu, v, o);
        if (lane == 0) warp_s[wrp] = v;
        __syncthreads();
        if (threadIdx.x == 0) {
            float t = 0.0f;
            #pragma unroll
            for (int j = 0; j < 8; ++j) t += warp_s[j];
            out[0] = t * (1.0f / (float)NL);
            g_cnt = 0;                 // restore for next graph replay
        }
    }
}

extern "C" void kernel_launch(void* const* d_in, const int* in_sizes, int n_in,
                              void* d_out, int out_size) {
    const float* y       = (const float*)d_in[0];  // (1,2,64,64,32) softmax; ch 0 used
    const float* sample  = (const float*)d_in[1];  // (1,1,64,64,32)
    const float* spacing = (const float*)d_in[2];  // (3,1)
    k_all<<<NBLK, TPB>>>(y, sample, spacing, (float*)d_out);
}

// round 8
// speedup vs baseline: 1.1335x; 1.1335x over previous
#include <cuda_runtime.h>
#include <cuda_bf16.h>

// N=1, C=2, H=64, W=64, D=32, radius=(3,3,1), SIGMA_XY=5, SIGMA_IMG=0.1, WEIGHT=1
#define NH 64
#define NW 64
#define ND 32
#define NL (NH * NW * ND)      // 131072

#define TPB  128
#define NBLK 512               // block = (h=2, w=4, d=32) slab = 256 voxels, 2 voxels/thread

// smem tile: h 9 x w 10 x d 34 halo'd neighborhood, packed (s, y0)
#define TH 9
#define TW 10
#define TD 34
#define TSTRW TD               // 34
#define TSTRH (TW * TD)        // 340
#define TSIZE (TH * TW * TD)   // 3060

#define SENTINEL 1e19f
#define LOG2E 1.4426950408889634f

__device__ float    g_part[NBLK];
__device__ unsigned g_cnt = 0;   // last block resets to 0 (graph-replay safe)

__device__ __forceinline__ float ex2(float x) {   // guaranteed MUFU EX2
    float r;
    asm("ex2.approx.f32 %0, %1;" : "=f"(r) : "f"(x));
    return r;
}

__global__ __launch_bounds__(TPB) void k_all(const float* __restrict__ y,
                                             const float* __restrict__ s,
                                             const float* __restrict__ spacing,
                                             float* __restrict__ out) {
    __shared__ float2 tile[TSIZE];
    __shared__ float  warp_s[4];

    // block -> slab origin
    const int hbase = (blockIdx.x >> 4) << 1;   // 0,2,...,62
    const int wbase = (blockIdx.x & 15) << 2;   // 0,4,...,60

    // ---- cooperative tile load (R5-style, branch-free predication) ----
    for (int i = threadIdx.x; i < TSIZE; i += TPB) {
        const int th = i / TSTRH;
        const int r  = i - th * TSTRH;
        const int tw = r / TD;
        const int td = r - tw * TD;
        const int gh = hbase + th - 3;
        const int gw = wbase + tw - 3;
        const int gd = td - 1;
        float2 v = make_float2(SENTINEL, 0.0f);
        if (((unsigned)gh < NH) & ((unsigned)gw < NW) & ((unsigned)gd < ND)) {
            const int gidx = (gh * NW + gw) * ND + gd;
            v = make_float2(__ldg(s + gidx), __ldg(y + gidx));
        }
        tile[i] = v;
    }
    __syncthreads();

    // thread -> 2 voxels: (hl, wl, dj) and (hl, wl, dj+16)
    const int dj = threadIdx.x & 15;            // 0..15
    const int wl = (threadIdx.x >> 4) & 3;      // 0..3
    const int hl = threadIdx.x >> 6;            // 0..1
    const int w  = wbase + wl;
    const int h  = hbase + hl;
    const int tb0 = (hl + 3) * TSTRH + (wl + 3) * TSTRW + (dj + 1);
    const int tb1 = tb0 + 16;

    const float2 c0a = tile[tb0];
    const float2 c0b = tile[tb1];
    const float sp0  = c0a.x, y0p0 = c0a.y;
    const float sp1  = c0b.x, y0p1 = c0b.y;
    const float m0   = 1.0f - 2.0f * y0p0;      // 1 - dot = y0p + m*y0q  (C=2 softmax)
    const float m1   = 1.0f - 2.0f * y0p1;

    const float sH = __ldg(spacing + 0);
    const float sW = __ldg(spacing + 1);
    const float sD = __ldg(spacing + 2);
    const float aH = sH * sH * (LOG2E / 50.0f);
    const float aW = sW * sW * (LOG2E / 50.0f);
    const float aD = sD * sD * (LOG2E / 50.0f);
    const float c2 = -50.0f * LOG2E;

    // Per-voxel split sums: tap term = k*(y0p + m*y0q) = y0p*K + m*KY
    float K0 = 0.0f, KY0 = 0.0f;
    float K1 = 0.0f, KY1 = 0.0f;

    // Half-space offsets (73 of 146 non-center taps); each in-bounds pair
    // counted once, doubled below (k and (1-dot) are p<->q symmetric).
    // Sentinel halo drives ex2 -> exactly 0: branch-free immediate-offset LDS.
    // Two voxels interleaved per tap: shared coff, independent chains (ILP).
    #pragma unroll
    for (int dz = 0; dz <= 1; ++dz) {
        #pragma unroll
        for (int dw = -3; dw <= 3; ++dw) {
            #pragma unroll
            for (int dh = -3; dh <= 3; ++dh) {
                if (dz == 0 && (dw < 0 || (dw == 0 && dh <= 0))) continue;
                const int off = dh * TSTRH + dw * TSTRW + dz;
                const float coff = -(aH * (float)(dh * dh)
                                   + aW * (float)(dw * dw)
                                   + aD * (float)(dz * dz));   // CSE'd constants
                const float2 cq0 = tile[tb0 + off];
                const float2 cq1 = tile[tb1 + off];
                const float ds0 = sp0 - cq0.x;
                const float ds1 = sp1 - cq1.x;
                const float e20 = fmaf(c2 * ds0, ds0, coff);
                const float e21 = fmaf(c2 * ds1, ds1, coff);
                const float k0  = ex2(e20);
                const float k1  = ex2(e21);
                K0 += k0;  KY0 = fmaf(k0, cq0.y, KY0);
                K1 += k1;  KY1 = fmaf(k1, cq1.y, KY1);
            }
        }
    }
    float acc = 2.0f * ((y0p0 * K0 + m0 * KY0) + (y0p1 * K1 + m1 * KY1));

    // OOB taps (zero-padded unfold): y-term 0; kernel value identical per
    // OOB offset: exp(-0.5*||f(p)||^2). Counted analytically, per voxel.
    const int cntH = min(h, 3) + min(NH - 1 - h, 3) + 1;
    const int cntW = min(w, 3) + min(NW - 1 - w, 3) + 1;
    const int hwc  = cntH * cntW;
    {
        const int d0 = dj;
        const int cntD0 = min(d0, 1) + min(ND - 1 - d0, 1) + 1;
        const int noob0 = 147 - hwc * cntD0;
        if (noob0) {
            const float e = -(aH * (float)(h * h) + aW * (float)(w * w) + aD * (float)(d0 * d0))
                            + c2 * sp0 * sp0;
            acc = fmaf((float)noob0, ex2(e), acc);
        }
        const int d1 = dj + 16;
        const int cntD1 = min(d1, 1) + min(ND - 1 - d1, 1) + 1;
        const int noob1 = 147 - hwc * cntD1;
        if (noob1) {
            const float e = -(aH * (float)(h * h) + aW * (float)(w * w) + aD * (float)(d1 * d1))
                            + c2 * sp1 * sp1;
            acc = fmaf((float)noob1, ex2(e), acc);
        }
    }

    // ---- block reduction ----
    #pragma unroll
    for (int o = 16; o; o >>= 1) acc += __shfl_down_sync(0xffffffffu, acc, o);
    const int lane = threadIdx.x & 31;
    const int wrp  = threadIdx.x >> 5;
    if (lane == 0) warp_s[wrp] = acc;
    __syncthreads();
    if (threadIdx.x == 0)
        g_part[blockIdx.x] = (warp_s[0] + warp_s[1]) + (warp_s[2] + warp_s[3]);

    // ---- last-block final reduction ----
    __threadfence();
    __shared__ bool is_last;
    if (threadIdx.x == 0)
        is_last = (atomicAdd(&g_cnt, 1u) == NBLK - 1);
    __syncthreads();

    if (is_last) {
        float v = 0.0f;
        #pragma unroll
        for (int j = 0; j < NBLK / TPB; ++j)
            v += g_part[threadIdx.x + j * TPB];
        #pragma unroll
        for (int o = 16; o; o >>= 1) v += __shfl_down_sync(0xffffffffu, v, o);
        if (lane == 0) warp_s[wrp] = v;
        __syncthreads();
        if (threadIdx.x == 0) {
            out[0] = ((warp_s[0] + warp_s[1]) + (warp_s[2] + warp_s[3])) * (1.0f / (float)NL);
            g_cnt = 0;                 // restore for next graph replay
        }
    }
}

extern "C" void kernel_launch(void* const* d_in, const int* in_sizes, int n_in,
                              void* d_out, int out_size) {
    const float* y       = (const float*)d_in[0];  // (1,2,64,64,32) softmax; ch 0 used
    const float* sample  = (const float*)d_in[1];  // (1,1,64,64,32)
    const float* spacing = (const float*)d_in[2];  // (3,1)
    k_all<<<NBLK, TPB>>>(y, sample, spacing, (float*)d_out);
}

// round 9
// speedup vs baseline: 1.1555x; 1.0194x over previous
#include <cuda_runtime.h>
#include <cuda_bf16.h>

// N=1, C=2, H=64, W=64, D=32, radius=(3,3,1), SIGMA_XY=5, SIGMA_IMG=0.1, WEIGHT=1
#define NH 64
#define NW 64
#define ND 32
#define NL (NH * NW * ND)      // 131072

#define TPB  128
#define NBLK 1024              // block = (h=1, w=4, d=32) slab, 1 voxel/thread

// smem tile: h 7 x w 10 x d 33, packed (s, y0).
// td = gd directly (half-space walk only needs dz in {0,1}); td=32 = sentinel.
#define TH 7
#define TW 10
#define TD 33
#define TSTRW TD               // 33
#define TSTRH (TW * TD)        // 330
#define TSIZE (TH * TW * TD)   // 2310
#define NROWS (TH * TW)        // 70

#define SENTINEL 1e19f
#define LOG2E 1.4426950408889634f

__device__ float    g_part[NBLK];
__device__ unsigned g_cnt = 0;   // last block resets to 0 (graph-replay safe)

__device__ __forceinline__ float ex2(float x) {   // guaranteed MUFU EX2
    float r;
    asm("ex2.approx.f32 %0, %1;" : "=f"(r) : "f"(x));
    return r;
}

__global__ __launch_bounds__(TPB) void k_all(const float* __restrict__ y,
                                             const float* __restrict__ s,
                                             const float* __restrict__ spacing,
                                             float* __restrict__ out) {
    __shared__ float2 tile[TSIZE];
    __shared__ float  warp_s[4];

    // block -> slab origin
    const int hbase = blockIdx.x >> 4;          // 0..63
    const int wbase = (blockIdx.x & 15) << 2;   // 0,4,...,60

    // ---- row-per-thread tile loader ----
    // Thread t < 70 owns tile row t = (th, tw): one div per THREAD, row-uniform
    // bounds, vectorized float4 global loads along the contiguous d axis.
    if (threadIdx.x < NROWS) {
        const int th = threadIdx.x / TW;
        const int tw = threadIdx.x - th * TW;
        const int gh = hbase + th - 3;
        const int gw = wbase + tw - 3;
        float2* rowp = &tile[threadIdx.x * TD];
        if (((unsigned)gh < NH) & ((unsigned)gw < NW)) {
            const int gbase = (gh * NW + gw) * ND;           // 128B-aligned
            const float4* s4 = (const float4*)(s + gbase);
            const float4* y4 = (const float4*)(y + gbase);
            #pragma unroll
            for (int j = 0; j < 8; ++j) {
                const float4 a = __ldg(s4 + j);
                const float4 b = __ldg(y4 + j);
                rowp[4 * j + 0] = make_float2(a.x, b.x);
                rowp[4 * j + 1] = make_float2(a.y, b.y);
                rowp[4 * j + 2] = make_float2(a.z, b.z);
                rowp[4 * j + 3] = make_float2(a.w, b.w);
            }
            rowp[32] = make_float2(SENTINEL, 0.0f);          // d-halo slot
        } else {
            #pragma unroll
            for (int j = 0; j < TD; ++j)
                rowp[j] = make_float2(SENTINEL, 0.0f);
        }
    }
    __syncthreads();

    // thread -> voxel
    const int d  = threadIdx.x & 31;
    const int wl = (threadIdx.x >> 5) & 3;      // 0..3
    const int w  = wbase + wl;
    const int h  = hbase;
    const int tb = 3 * TSTRH + (wl + 3) * TSTRW + d;

    const float2 c0 = tile[tb];
    const float sp  = c0.x;
    const float y0p = c0.y;
    const float m   = 1.0f - 2.0f * y0p;        // 1 - dot = y0p + m*y0q  (C=2 softmax)

    const float sH = __ldg(spacing + 0);
    const float sW = __ldg(spacing + 1);
    const float sD = __ldg(spacing + 2);
    const float aH = sH * sH * (LOG2E / 50.0f);
    const float aW = sW * sW * (LOG2E / 50.0f);
    const float aD = sD * sD * (LOG2E / 50.0f);
    const float c2 = -50.0f * LOG2E;

    // Split sums: tap term = k*(y0p + m*y0q) = y0p*K + m*KY
    float K0 = 0.0f, K1 = 0.0f, KY0 = 0.0f, KY1 = 0.0f;
    int tap = 0;

    // Half-space offsets (73 of 146 non-center taps); each in-bounds pair
    // counted once, doubled below (k and (1-dot) are p<->q symmetric).
    // Sentinel halo drives ex2 -> exactly 0: branch-free immediate-offset LDS.
    #pragma unroll
    for (int dz = 0; dz <= 1; ++dz) {
        #pragma unroll
        for (int dw = -3; dw <= 3; ++dw) {
            #pragma unroll
            for (int dh = -3; dh <= 3; ++dh) {
                if (dz == 0 && (dw < 0 || (dw == 0 && dh <= 0))) continue;
                const float2 cq = tile[tb + dh * TSTRH + dw * TSTRW + dz];
                const float coff = -(aH * (float)(dh * dh)
                                   + aW * (float)(dw * dw)
                                   + aD * (float)(dz * dz));   // CSE'd constants
                const float ds = sp - cq.x;
                const float e2 = fmaf(c2 * ds, ds, coff);
                const float k  = ex2(e2);
                if (tap & 1) { K1 += k; KY1 = fmaf(k, cq.y, KY1); }
                else         { K0 += k; KY0 = fmaf(k, cq.y, KY0); }
                ++tap;
            }
        }
    }
    float acc = 2.0f * (y0p * (K0 + K1) + m * (KY0 + KY1));

    // OOB taps (zero-padded unfold): y-term 0; kernel value identical per
    // OOB offset: exp(-0.5*||f(p)||^2). Count analytically.
    const int cntH = min(h, 3) + min(NH - 1 - h, 3) + 1;
    const int cntW = min(w, 3) + min(NW - 1 - w, 3) + 1;
    const int cntD = min(d, 1) + min(ND - 1 - d, 1) + 1;
    const int noob = 147 - cntH * cntW * cntD;
    if (noob) {
        const float e = -(aH * (float)(h * h) + aW * (float)(w * w) + aD * (float)(d * d))
                        + c2 * sp * sp;
        acc = fmaf((float)noob, ex2(e), acc);
    }

    // ---- block reduction ----
    #pragma unroll
    for (int o = 16; o; o >>= 1) acc += __shfl_down_sync(0xffffffffu, acc, o);
    const int lane = threadIdx.x & 31;
    const int wrp  = threadIdx.x >> 5;
    if (lane == 0) warp_s[wrp] = acc;
    __syncthreads();
    if (threadIdx.x == 0)
        g_part[blockIdx.x] = (warp_s[0] + warp_s[1]) + (warp_s[2] + warp_s[3]);

    // ---- last-block final reduction ----
    __threadfence();
    __shared__ bool is_last;
    if (threadIdx.x == 0)
        is_last = (atomicAdd(&g_cnt, 1u) == NBLK - 1);
    __syncthreads();

    if (is_last) {
        float v = 0.0f;
        #pragma unroll
        for (int j = 0; j < NBLK / TPB; ++j)
            v += g_part[threadIdx.x + j * TPB];
        #pragma unroll
        for (int o = 16; o; o >>= 1) v += __shfl_down_sync(0xffffffffu, v, o);
        if (lane == 0) warp_s[wrp] = v;
        __syncthreads();
        if (threadIdx.x == 0) {
            out[0] = ((warp_s[0] + warp_s[1]) + (warp_s[2] + warp_s[3])) * (1.0f / (float)NL);
            g_cnt = 0;                 // restore for next graph replay
        }
    }
}

extern "C" void kernel_launch(void* const* d_in, const int* in_sizes, int n_in,
                              void* d_out, int out_size) {
    const float* y       = (const float*)d_in[0];  // (1,2,64,64,32) softmax; ch 0 used
    const float* sample  = (const float*)d_in[1];  // (1,1,64,64,32)
    const float* spacing = (const float*)d_in[2];  // (3,1)
    k_all<<<NBLK, TPB>>>(y, sample, spacing, (float*)d_out);
}

// round 10
// speedup vs baseline: 1.1810x; 1.0221x over previous
#include <cuda_runtime.h>
#include <cuda_bf16.h>

// N=1, C=2, H=64, W=64, D=32, radius=(3,3,1), SIGMA_XY=5, SIGMA_IMG=0.1, WEIGHT=1
#define NH 64
#define NW 64
#define ND 32
#define NL (NH * NW * ND)      // 131072

#define TPB  128
#define NBLK 1024              // block = (h=1, w=4, d=32) slab, 1 voxel/thread

// smem tile: h 7 x w 10 x d 33, packed (s, y0).
// td = gd directly (half-space walk only needs dz in {0,1}); td=32 = sentinel.
#define TH 7
#define TW 10
#define TD 33
#define TSTRW TD               // 33
#define TSTRH (TW * TD)        // 330
#define TSIZE (TH * TW * TD)   // 2310
#define NROWS (TH * TW)        // 70

#define SENTINEL 1e19f
#define LOG2E 1.4426950408889634f

__device__ float    g_part[NBLK];
__device__ unsigned g_cnt = 0;   // last block resets to 0 (graph-replay safe)

__device__ __forceinline__ float ex2(float x) {   // guaranteed MUFU EX2
    float r;
    asm("ex2.approx.f32 %0, %1;" : "=f"(r) : "f"(x));
    return r;
}

__global__ __launch_bounds__(TPB) void k_all(const float* __restrict__ y,
                                             const float* __restrict__ s,
                                             const float* __restrict__ spacing,
                                             float* __restrict__ out) {
    __shared__ float2 tile[TSIZE];
    __shared__ int    rowbase[NROWS];   // gmem row base, or -1 if OOB row
    __shared__ float  warp_s[4];

    const int lane = threadIdx.x & 31;
    const int wrp  = threadIdx.x >> 5;          // 0..3

    // block -> slab origin
    const int hbase = blockIdx.x >> 4;          // 0..63
    const int wbase = (blockIdx.x & 15) << 2;   // 0,4,...,60

    // ---- row descriptors (one div per ROW, once) + d-halo sentinel column ----
    if (threadIdx.x < NROWS) {
        const int th = threadIdx.x / TW;
        const int tw = threadIdx.x - th * TW;
        const int gh = hbase + th - 3;
        const int gw = wbase + tw - 3;
        rowbase[threadIdx.x] = (((unsigned)gh < NH) & ((unsigned)gw < NW))
                                   ? (gh * NW + gw) * ND : -1;
        tile[threadIdx.x * TD + 32] = make_float2(SENTINEL, 0.0f);
    }
    __syncthreads();

    // ---- warp-row loader: lanes along d => fully coalesced LDG.32 pairs,
    // conflict-free STS.64; per-iteration control is warp-uniform. ----
    #pragma unroll
    for (int r = wrp; r < NROWS; r += 4) {
        const int gb = rowbase[r];              // uniform LDS broadcast
        float2 v = make_float2(SENTINEL, 0.0f);
        if (gb >= 0)                            // warp-uniform predicate
            v = make_float2(__ldg(s + gb + lane), __ldg(y + gb + lane));
        tile[r * TD + lane] = v;
    }
    __syncthreads();

    // thread -> voxel
    const int d  = lane;
    const int wl = wrp;                         // 0..3
    const int w  = wbase + wl;
    const int h  = hbase;
    const int tb = 3 * TSTRH + (wl + 3) * TSTRW + d;

    const float2 c0 = tile[tb];
    const float sp  = c0.x;
    const float y0p = c0.y;
    const float m   = 1.0f - 2.0f * y0p;        // 1 - dot = y0p + m*y0q  (C=2 softmax)

    const float sH = __ldg(spacing + 0);
    const float sW = __ldg(spacing + 1);
    const float sD = __ldg(spacing + 2);
    const float aH = sH * sH * (LOG2E / 50.0f);
    const float aW = sW * sW * (LOG2E / 50.0f);
    const float aD = sD * sD * (LOG2E / 50.0f);
    const float c2 = -50.0f * LOG2E;

    // Split sums: tap term = k*(y0p + m*y0q) = y0p*K + m*KY
    float K0 = 0.0f, K1 = 0.0f, KY0 = 0.0f, KY1 = 0.0f;
    int tap = 0;

    // Half-space offsets (73 of 146 non-center taps); each in-bounds pair
    // counted once, doubled below (k and (1-dot) are p<->q symmetric).
    // Sentinel halo drives ex2 -> exactly 0: branch-free immediate-offset LDS.
    #pragma unroll
    for (int dz = 0; dz <= 1; ++dz) {
        #pragma unroll
        for (int dw = -3; dw <= 3; ++dw) {
            #pragma unroll
            for (int dh = -3; dh <= 3; ++dh) {
                if (dz == 0 && (dw < 0 || (dw == 0 && dh <= 0))) continue;
                const float2 cq = tile[tb + dh * TSTRH + dw * TSTRW + dz];
                const float coff = -(aH * (float)(dh * dh)
                                   + aW * (float)(dw * dw)
                                   + aD * (float)(dz * dz));   // CSE'd constants
                const float ds = sp - cq.x;
                const float e2 = fmaf(c2 * ds, ds, coff);
                const float k  = ex2(e2);
                if (tap & 1) { K1 += k; KY1 = fmaf(k, cq.y, KY1); }
                else         { K0 += k; KY0 = fmaf(k, cq.y, KY0); }
                ++tap;
            }
        }
    }
    float acc = 2.0f * (y0p * (K0 + K1) + m * (KY0 + KY1));

    // OOB taps (zero-padded unfold): y-term 0; kernel value identical per
    // OOB offset: exp(-0.5*||f(p)||^2). Count analytically.
    const int cntH = min(h, 3) + min(NH - 1 - h, 3) + 1;
    const int cntW = min(w, 3) + min(NW - 1 - w, 3) + 1;
    const int cntD = min(d, 1) + min(ND - 1 - d, 1) + 1;
    const int noob = 147 - cntH * cntW * cntD;
    if (noob) {
        const float e = -(aH * (float)(h * h) + aW * (float)(w * w) + aD * (float)(d * d))
                        + c2 * sp * sp;
        acc = fmaf((float)noob, ex2(e), acc);
    }

    // ---- block reduction ----
    #pragma unroll
    for (int o = 16; o; o >>= 1) acc += __shfl_down_sync(0xffffffffu, acc, o);
    if (lane == 0) warp_s[wrp] = acc;
    __syncthreads();
    if (threadIdx.x == 0)
        g_part[blockIdx.x] = (warp_s[0] + warp_s[1]) + (warp_s[2] + warp_s[3]);

    // ---- last-block final reduction ----
    __threadfence();
    __shared__ bool is_last;
    if (threadIdx.x == 0)
        is_last = (atomicAdd(&g_cnt, 1u) == NBLK - 1);
    __syncthreads();

    if (is_last) {
        float v = 0.0f;
        #pragma unroll
        for (int j = 0; j < NBLK / TPB; ++j)
            v += g_part[threadIdx.x + j * TPB];
        #pragma unroll
        for (int o = 16; o; o >>= 1) v += __shfl_down_sync(0xffffffffu, v, o);
        if (lane == 0) warp_s[wrp] = v;
        __syncthreads();
        if (threadIdx.x == 0) {
            out[0] = ((warp_s[0] + warp_s[1]) + (warp_s[2] + warp_s[3])) * (1.0f / (float)NL);
            g_cnt = 0;                 // restore for next graph replay
        }
    }
}

extern "C" void kernel_launch(void* const* d_in, const int* in_sizes, int n_in,
                              void* d_out, int out_size) {
    const float* y       = (const float*)d_in[0];  // (1,2,64,64,32) softmax; ch 0 used
    const float* sample  = (const float*)d_in[1];  // (1,1,64,64,32)
    const float* spacing = (const float*)d_in[2];  // (3,1)
    k_all<<<NBLK, TPB>>>(y, sample, spacing, (float*)d_out);
}

// round 11
// speedup vs baseline: 1.3177x; 1.1158x over previous
#include <cuda_runtime.h>
#include <cuda_bf16.h>

// N=1, C=2, H=64, W=64, D=32, radius=(3,3,1), SIGMA_XY=5, SIGMA_IMG=0.1, WEIGHT=1
#define NH 64
#define NW 64
#define ND 32
#define NL (NH * NW * ND)      // 131072

#define TPB  128
#define NBLK 1024              // block = (h=2, w=2, d=32) slab = 128 voxels, 1 voxel/thread

// smem tile: (8, 8, 32) pow2 strides; td = gd directly (dz walk only needs d, d+1).
#define TSTRH 256
#define TSTRW 32
#define TSIZE 2048             // +1 pad element for the corner dz=1 read

#define SENTINEL 1e19f
#define LOG2E 1.4426950408889634f

__device__ float    g_part[NBLK];
__device__ unsigned g_cnt = 0;   // last block resets to 0 (graph-replay safe)

__device__ __forceinline__ float ex2(float x) {   // guaranteed MUFU EX2
    float r;
    asm("ex2.approx.f32 %0, %1;" : "=f"(r) : "f"(x));
    return r;
}

__global__ __launch_bounds__(TPB) void k_all(const float* __restrict__ y,
                                             const float* __restrict__ s,
                                             const float* __restrict__ spacing,
                                             float* __restrict__ out) {
    __shared__ float2 tile[TSIZE + 1];
    __shared__ float  warp_s[4];

    // block -> slab origin (32 x 32 grid of 2x2 slabs)
    const int hbase = (blockIdx.x >> 5) << 1;   // 0,2,...,62
    const int wbase = (blockIdx.x & 31) << 1;   // 0,2,...,62

    // ---- cooperative tile load: pow2 index math, independent coalesced LDGs ----
    #pragma unroll
    for (int j = 0; j < TSIZE / TPB; ++j) {
        const int i  = threadIdx.x + j * TPB;
        const int th = i >> 8;                  // 0..7
        const int tw = (i >> 5) & 7;            // 0..7
        const int td = i & 31;
        const int gh = hbase + th - 3;          // -3..4 around the 2-slab
        const int gw = wbase + tw - 3;
        float2 v = make_float2(SENTINEL, 0.0f);
        if (((unsigned)gh < NH) & ((unsigned)gw < NW)) {
            const int gidx = (gh * NW + gw) * ND + td;
            v = make_float2(__ldg(s + gidx), __ldg(y + gidx));
        }
        tile[i] = v;
    }
    if (threadIdx.x == 0) tile[TSIZE] = make_float2(SENTINEL, 0.0f);  // corner pad
    __syncthreads();

    // thread -> voxel
    const int d  = threadIdx.x & 31;
    const int wl = (threadIdx.x >> 5) & 1;      // 0..1
    const int hl = threadIdx.x >> 6;            // 0..1
    const int w  = wbase + wl;
    const int h  = hbase + hl;
    const int tb = (hl + 3) * TSTRH + (wl + 3) * TSTRW + d;

    const float2 c0 = tile[tb];
    const float sp  = c0.x;
    const float y0p = c0.y;
    const float m   = 1.0f - 2.0f * y0p;        // 1 - dot = y0p + m*y0q  (C=2 softmax)

    const float sH = __ldg(spacing + 0);
    const float sW = __ldg(spacing + 1);
    const float sD = __ldg(spacing + 2);
    const float aH = sH * sH * (LOG2E / 50.0f);
    const float aW = sW * sW * (LOG2E / 50.0f);
    const float aD = sD * sD * (LOG2E / 50.0f);
    const float c2 = -50.0f * LOG2E;

    // dz=0 taps -> Ka/KYa (always valid). dz=1 taps -> Kb/KYb, valid iff d<31
    // (d=31's dz=1 reads wrap into the next row; those taps are the OOB set,
    //  already counted analytically below, so they are masked out exactly).
    float Ka = 0.0f, KYa = 0.0f, Kb = 0.0f, KYb = 0.0f;

    // Half-space offsets (73 of 146 non-center taps); each in-bounds pair
    // counted once, doubled below (k and (1-dot) are p<->q symmetric).
    // Sentinel halo (h/w OOB rows) drives ex2 -> exactly 0: branch-free LDS.
    #pragma unroll
    for (int dz = 0; dz <= 1; ++dz) {
        #pragma unroll
        for (int dw = -3; dw <= 3; ++dw) {
            #pragma unroll
            for (int dh = -3; dh <= 3; ++dh) {
                if (dz == 0 && (dw < 0 || (dw == 0 && dh <= 0))) continue;
                const float2 cq = tile[tb + dh * TSTRH + dw * TSTRW + dz];
                const float coff = -(aH * (float)(dh * dh)
                                   + aW * (float)(dw * dw)
                                   + aD * (float)(dz * dz));   // CSE'd constants
                const float ds = sp - cq.x;
                const float e2 = fmaf(c2 * ds, ds, coff);
                const float k  = ex2(e2);
                if (dz == 0) { Ka += k; KYa = fmaf(k, cq.y, KYa); }
                else         { Kb += k; KYb = fmaf(k, cq.y, KYb); }
            }
        }
    }
    const float maskD = (d < ND - 1) ? 1.0f : 0.0f;
    const float K  = fmaf(maskD, Kb,  Ka);
    const float KY = fmaf(maskD, KYb, KYa);
    float acc = 2.0f * (y0p * K + m * KY);

    // OOB taps (zero-padded unfold): y-term 0; kernel value identical per
    // OOB offset: exp(-0.5*||f(p)||^2). Count analytically.
    const int cntH = min(h, 3) + min(NH - 1 - h, 3) + 1;
    const int cntW = min(w, 3) + min(NW - 1 - w, 3) + 1;
    const int cntD = min(d, 1) + min(ND - 1 - d, 1) + 1;
    const int noob = 147 - cntH * cntW * cntD;
    if (noob) {
        const float e = -(aH * (float)(h * h) + aW * (float)(w * w) + aD * (float)(d * d))
                        + c2 * sp * sp;
        acc = fmaf((float)noob, ex2(e), acc);
    }

    // ---- block reduction ----
    #pragma unroll
    for (int o = 16; o; o >>= 1) acc += __shfl_down_sync(0xffffffffu, acc, o);
    const int lane = threadIdx.x & 31;
    const int wrp  = threadIdx.x >> 5;
    if (lane == 0) warp_s[wrp] = acc;
    __syncthreads();
    if (threadIdx.x == 0)
        g_part[blockIdx.x] = (warp_s[0] + warp_s[1]) + (warp_s[2] + warp_s[3]);

    // ---- last-block final reduction ----
    __threadfence();
    __shared__ bool is_last;
    if (threadIdx.x == 0)
        is_last = (atomicAdd(&g_cnt, 1u) == NBLK - 1);
    __syncthreads();

    if (is_last) {
        float v = 0.0f;
        #pragma unroll
        for (int j = 0; j < NBLK / TPB; ++j)
            v += g_part[threadIdx.x + j * TPB];
        #pragma unroll
        for (int o = 16; o; o >>= 1) v += __shfl_down_sync(0xffffffffu, v, o);
        if (lane == 0) warp_s[wrp] = v;
        __syncthreads();
        if (threadIdx.x == 0) {
            out[0] = ((warp_s[0] + warp_s[1]) + (warp_s[2] + warp_s[3])) * (1.0f / (float)NL);
            g_cnt = 0;                 // restore for next graph replay
        }
    }
}

extern "C" void kernel_launch(void* const* d_in, const int* in_sizes, int n_in,
                              void* d_out, int out_size) {
    const float* y       = (const float*)d_in[0];  // (1,2,64,64,32) softmax; ch 0 used
    const float* sample  = (const float*)d_in[1];  // (1,1,64,64,32)
    const float* spacing = (const float*)d_in[2];  // (3,1)
    k_all<<<NBLK, TPB>>>(y, sample, spacing, (float*)d_out);
}

// round 12
// speedup vs baseline: 1.3375x; 1.0150x over previous
#include <cuda_runtime.h>
#include <cuda_bf16.h>

// N=1, C=2, H=64, W=64, D=32, radius=(3,3,1), SIGMA_XY=5, SIGMA_IMG=0.1, WEIGHT=1
#define NH 64
#define NW 64
#define ND 32
#define NL (NH * NW * ND)      // 131072

#define TPB  128
#define NBLK 1024              // block = (h=2, w=2, d=32) slab = 128 voxels, 1 voxel/thread

// smem tile: (8, 8, 32) pow2 strides; td = gd directly (dz walk only needs d, d+1).
#define TSTRH 256
#define TSTRW 32
#define TSIZE 2048             // +1 pad element for the corner dz=1 read

#define SENTINEL 1e19f
#define LOG2E 1.4426950408889634f

__device__ float    g_part[NBLK];
__device__ unsigned g_cnt = 0;   // last block resets to 0 (graph-replay safe)

__device__ __forceinline__ float ex2(float x) {   // guaranteed MUFU EX2
    float r;
    asm("ex2.approx.f32 %0, %1;" : "=f"(r) : "f"(x));
    return r;
}

__global__ __launch_bounds__(TPB, 8) void k_all(const float* __restrict__ y,
                                                const float* __restrict__ s,
                                                const float* __restrict__ spacing,
                                                float* __restrict__ out) {
    __shared__ float2 tile[TSIZE + 1];
    __shared__ float  warp_s[4];

    // block -> slab origin (32 x 32 grid of 2x2 slabs)
    const int hbase = (blockIdx.x >> 5) << 1;   // 0,2,...,62
    const int wbase = (blockIdx.x & 31) << 1;   // 0,2,...,62

    // ---- cooperative tile load: pow2 index math, independent coalesced LDGs ----
    #pragma unroll
    for (int j = 0; j < TSIZE / TPB; ++j) {
        const int i  = threadIdx.x + j * TPB;
        const int th = i >> 8;                  // 0..7
        const int tw = (i >> 5) & 7;            // 0..7
        const int td = i & 31;
        const int gh = hbase + th - 3;
        const int gw = wbase + tw - 3;
        float2 v = make_float2(SENTINEL, 0.0f);
        if (((unsigned)gh < NH) & ((unsigned)gw < NW)) {
            const int gidx = (gh * NW + gw) * ND + td;
            v = make_float2(__ldg(s + gidx), __ldg(y + gidx));
        }
        tile[i] = v;
    }
    if (threadIdx.x == 0) tile[TSIZE] = make_float2(SENTINEL, 0.0f);  // corner pad
    __syncthreads();

    // thread -> voxel
    const int d  = threadIdx.x & 31;
    const int wl = (threadIdx.x >> 5) & 1;      // 0..1
    const int hl = threadIdx.x >> 6;            // 0..1
    const int w  = wbase + wl;
    const int h  = hbase + hl;
    const int tb = (hl + 3) * TSTRH + (wl + 3) * TSTRW + d;

    const float2 c0 = tile[tb];
    const float sp  = c0.x;
    const float y0p = c0.y;
    const float m   = 1.0f - 2.0f * y0p;        // 1 - dot = y0p + m*y0q  (C=2 softmax)

    const float sH = __ldg(spacing + 0);
    const float sW = __ldg(spacing + 1);
    const float sD = __ldg(spacing + 2);
    const float aH = sH * sH * (LOG2E / 50.0f);
    const float aW = sW * sW * (LOG2E / 50.0f);
    const float aD = sD * sD * (LOG2E / 50.0f);
    const float c2 = -50.0f * LOG2E;

    // Register-resident spatial constants: 16 distinct (|dh|,|dw|) combos.
    // The dz=1 constant factor 2^(-aD) is hoisted OUT of the loop entirely:
    // dz=1 taps accumulate without it, and Kb/KYb are scaled once at the end.
    float coffs[16];
    #pragma unroll
    for (int ih = 0; ih < 4; ++ih) {
        const float vH = -aH * (float)(ih * ih);
        #pragma unroll
        for (int iw = 0; iw < 4; ++iw)
            coffs[ih * 4 + iw] = fmaf(-aW, (float)(iw * iw), vH);
    }

    // dz=0 taps -> Ka/KYa (always valid). dz=1 taps -> Kb/KYb (valid iff d<31;
    // d=31's dz=1 reads wrap into the next row but are the analytic-OOB set,
    // masked exactly below).
    float Ka = 0.0f, KYa = 0.0f, Kb = 0.0f, KYb = 0.0f;

    // Half-space offsets (73 of 146 non-center taps); each in-bounds pair
    // counted once, doubled below (k and (1-dot) are p<->q symmetric).
    // Sentinel halo (h/w OOB rows) drives ex2 -> exactly 0: branch-free LDS.
    #pragma unroll
    for (int dz = 0; dz <= 1; ++dz) {
        #pragma unroll
        for (int dw = -3; dw <= 3; ++dw) {
            #pragma unroll
            for (int dh = -3; dh <= 3; ++dh) {
                if (dz == 0 && (dw < 0 || (dw == 0 && dh <= 0))) continue;
                const int ih = dh < 0 ? -dh : dh;           // compile-time
                const int iw = dw < 0 ? -dw : dw;           // compile-time
                const float2 cq = tile[tb + dh * TSTRH + dw * TSTRW + dz];
                const float ds = sp - cq.x;
                const float e2 = fmaf(c2 * ds, ds, coffs[ih * 4 + iw]);
                const float k  = ex2(e2);
                if (dz == 0) { Ka += k; KYa = fmaf(k, cq.y, KYa); }
                else         { Kb += k; KYb = fmaf(k, cq.y, KYb); }
            }
        }
    }
    const float maskD = (d < ND - 1) ? 1.0f : 0.0f;
    const float scaleZ = maskD * ex2(-aD);      // dz=1 spatial factor, hoisted
    const float K  = fmaf(scaleZ, Kb,  Ka);
    const float KY = fmaf(scaleZ, KYb, KYa);
    float acc = 2.0f * (y0p * K + m * KY);

    // OOB taps (zero-padded unfold): y-term 0; kernel value identical per
    // OOB offset: exp(-0.5*||f(p)||^2). Count analytically.
    const int cntH = min(h, 3) + min(NH - 1 - h, 3) + 1;
    const int cntW = min(w, 3) + min(NW - 1 - w, 3) + 1;
    const int cntD = min(d, 1) + min(ND - 1 - d, 1) + 1;
    const int noob = 147 - cntH * cntW * cntD;
    if (noob) {
        const float e = -(aH * (float)(h * h) + aW * (float)(w * w) + aD * (float)(d * d))
                        + c2 * sp * sp;
        acc = fmaf((float)noob, ex2(e), acc);
    }

    // ---- block reduction ----
    #pragma unroll
    for (int o = 16; o; o >>= 1) acc += __shfl_down_sync(0xffffffffu, acc, o);
    const int lane = threadIdx.x & 31;
    const int wrp  = threadIdx.x >> 5;
    if (lane == 0) warp_s[wrp] = acc;
    __syncthreads();
    if (threadIdx.x == 0)
        g_part[blockIdx.x] = (warp_s[0] + warp_s[1]) + (warp_s[2] + warp_s[3]);

    // ---- last-block final reduction ----
    __threadfence();
    __shared__ bool is_last;
    if (threadIdx.x == 0)
        is_last = (atomicAdd(&g_cnt, 1u) == NBLK - 1);
    __syncthreads();

    if (is_last) {
        float v = 0.0f;
        #pragma unroll
        for (int j = 0; j < NBLK / TPB; ++j)
            v += g_part[threadIdx.x + j * TPB];
        #pragma unroll
        for (int o = 16; o; o >>= 1) v += __shfl_down_sync(0xffffffffu, v, o);
        if (lane == 0) warp_s[wrp] = v;
        __syncthreads();
        if (threadIdx.x == 0) {
            out[0] = ((warp_s[0] + warp_s[1]) + (warp_s[2] + warp_s[3])) * (1.0f / (float)NL);
            g_cnt = 0;                 // restore for next graph replay
        }
    }
}

extern "C" void kernel_launch(void* const* d_in, const int* in_sizes, int n_in,
                              void* d_out, int out_size) {
    const float* y       = (const float*)d_in[0];  // (1,2,64,64,32) softmax; ch 0 used
    const float* sample  = (const float*)d_in[1];  // (1,1,64,64,32)
    const float* spacing = (const float*)d_in[2];  // (3,1)
    k_all<<<NBLK, TPB>>>(y, sample, spacing, (float*)d_out);
}